// round 6
// baseline (speedup 1.0000x reference)
#include <cuda_runtime.h>
#include <cuda_bf16.h>
#include <math.h>

// Problem constants (fixed by the reference setup_inputs)
#define BB 1024
#define AA 64
#define DD 1024
#define D4 (DD / 4)        // 256 float4 per row
#define EPS 1e-8f

// Device-global accumulators (no allocation allowed)
__device__ float g_kl_sum;
__device__ float g_ndcg_sum;

__global__ void zero_kernel() {
    g_kl_sum = 0.0f;
    g_ndcg_sum = 0.0f;
}

__device__ __forceinline__ float warp_sum(float v) {
    #pragma unroll
    for (int o = 16; o > 0; o >>= 1) v += __shfl_xor_sync(0xFFFFFFFFu, v, o);
    return v;
}
__device__ __forceinline__ float warp_max(float v) {
    #pragma unroll
    for (int o = 16; o > 0; o >>= 1) v = fmaxf(v, __shfl_xor_sync(0xFFFFFFFFu, v, o));
    return v;
}

__global__ __launch_bounds__(512, 2)
void listwise_kernel(const float* __restrict__ q,
                     const float* __restrict__ a_emb,
                     const float* __restrict__ scores) {
    const int b    = blockIdx.x;
    const int tid  = threadIdx.x;
    const int warp = tid >> 5;
    const int lane = tid & 31;

    __shared__ float s_q[DD];
    __shared__ float s_sim[AA];
    __shared__ float s_sc[AA];

    // Cooperative load of q[b] (4 KB) into smem, coalesced float4.
    {
        const float4* q4 = reinterpret_cast<const float4*>(q + (size_t)b * DD);
        float4* sq4 = reinterpret_cast<float4*>(s_q);
        if (tid < D4) sq4[tid] = q4[tid];
    }
    if (tid < AA) s_sc[tid] = scores[(size_t)b * AA + tid];
    __syncthreads();

    // Each warp handles answers {warp, warp+16, warp+32, warp+48}.
    // Cache this warp's q slice (32 floats) in registers, reuse across 4 answers.
    float4 qv[8];
    {
        const float4* sq4 = reinterpret_cast<const float4*>(s_q);
        #pragma unroll
        for (int it = 0; it < 8; it++) qv[it] = sq4[it * 32 + lane];
    }

    const float4* Ab = reinterpret_cast<const float4*>(a_emb) + (size_t)b * AA * D4;
    float acc0 = 0.f, acc1 = 0.f, acc2 = 0.f, acc3 = 0.f;

    #pragma unroll
    for (int it = 0; it < 8; it++) {
        const int off = it * 32 + lane;
        float4 v0 = Ab[(size_t)(warp +  0) * D4 + off];
        float4 v1 = Ab[(size_t)(warp + 16) * D4 + off];
        float4 v2 = Ab[(size_t)(warp + 32) * D4 + off];
        float4 v3 = Ab[(size_t)(warp + 48) * D4 + off];
        float4 qq = qv[it];
        acc0 = fmaf(v0.x, qq.x, acc0); acc0 = fmaf(v0.y, qq.y, acc0);
        acc0 = fmaf(v0.z, qq.z, acc0); acc0 = fmaf(v0.w, qq.w, acc0);
        acc1 = fmaf(v1.x, qq.x, acc1); acc1 = fmaf(v1.y, qq.y, acc1);
        acc1 = fmaf(v1.z, qq.z, acc1); acc1 = fmaf(v1.w, qq.w, acc1);
        acc2 = fmaf(v2.x, qq.x, acc2); acc2 = fmaf(v2.y, qq.y, acc2);
        acc2 = fmaf(v2.z, qq.z, acc2); acc2 = fmaf(v2.w, qq.w, acc2);
        acc3 = fmaf(v3.x, qq.x, acc3); acc3 = fmaf(v3.y, qq.y, acc3);
        acc3 = fmaf(v3.z, qq.z, acc3); acc3 = fmaf(v3.w, qq.w, acc3);
    }

    acc0 = warp_sum(acc0);
    acc1 = warp_sum(acc1);
    acc2 = warp_sum(acc2);
    acc3 = warp_sum(acc3);
    if (lane == 0) {
        s_sim[warp +  0] = acc0;
        s_sim[warp + 16] = acc1;
        s_sim[warp + 32] = acc2;
        s_sim[warp + 48] = acc3;
    }
    __syncthreads();

    // ---- Epilogue on warp 0: softmax, KL, NDCG over A=64 (2 answers/lane) ----
    if (warp == 0) {
        const int a0 = lane;
        const int a1 = lane + 32;
        const float si0 = s_sim[a0], si1 = s_sim[a1];
        const float sc0 = s_sc[a0],  sc1 = s_sc[a1];

        // softmax over sim
        float m  = warp_max(fmaxf(si0, si1));
        float e0 = expf(si0 - m), e1 = expf(si1 - m);
        float Z  = warp_sum(e0 + e1);
        float p0 = e0 / Z, p1 = e1 / Z;

        // softmax over target scores (T=1)
        float ms = warp_max(fmaxf(sc0, sc1));
        float t0 = expf(sc0 - ms), t1 = expf(sc1 - ms);
        float Zt = warp_sum(t0 + t1);
        float logZt = logf(Zt);

        // KL(target || pred), reduction = sum over A
        float lt0 = (sc0 - ms) - logZt;              // log target_probs
        float lt1 = (sc1 - ms) - logZt;
        float kl  = (t0 / Zt) * (lt0 - logf(p0 + EPS))
                  + (t1 / Zt) * (lt1 - logf(p1 + EPS));
        kl = warp_sum(kl);

        // ranks (0-indexed), stable tie-break by index == jax stable argsort(-x)
        int r0 = 0, r1 = 0, i0 = 0, i1 = 0;
        #pragma unroll
        for (int j = 0; j < AA; j++) {
            float sj = s_sim[j];
            float cj = s_sc[j];
            r0 += (sj > si0) || (sj == si0 && j < a0);
            r1 += (sj > si1) || (sj == si1 && j < a1);
            i0 += (cj > sc0) || (cj == sc0 && j < a0);
            i1 += (cj > sc1) || (cj == sc1 && j < a1);
        }
        float pred_dcg  = sc0 / log2f((float)(r0 + 2)) + sc1 / log2f((float)(r1 + 2));
        float ideal_dcg = sc0 / log2f((float)(i0 + 2)) + sc1 / log2f((float)(i1 + 2));
        pred_dcg  = warp_sum(pred_dcg);
        ideal_dcg = warp_sum(ideal_dcg);

        if (lane == 0) {
            atomicAdd(&g_kl_sum, kl);
            atomicAdd(&g_ndcg_sum, pred_dcg / (ideal_dcg + EPS));
        }
    }
}

__global__ void finalize_kernel(float* __restrict__ out, int out_size) {
    if (threadIdx.x == 0) {
        out[0] = g_kl_sum / (float)BB;           // loss
        if (out_size > 1) out[1] = g_ndcg_sum / (float)BB;  // avg_ndcg
    }
}

extern "C" void kernel_launch(void* const* d_in, const int* in_sizes, int n_in,
                              void* d_out, int out_size) {
    const float* q      = (const float*)d_in[0];   // [B, D]
    const float* a_emb  = (const float*)d_in[1];   // [B, A, D]
    const float* scores = (const float*)d_in[2];   // [B, A]
    (void)in_sizes; (void)n_in;
    float* out = (float*)d_out;

    zero_kernel<<<1, 1>>>();
    listwise_kernel<<<BB, 512>>>(q, a_emb, scores);
    finalize_kernel<<<1, 32>>>(out, out_size);
}